// round 7
// baseline (speedup 1.0000x reference)
#include <cuda_runtime.h>
#include <cstdint>

#define NB 8
#define LQ 8192
#define SK 8192
#define HH 8
#define DD 32
#define NH (NB*HH)
#define EPSV 1e-6f

// pass1
#define CHUNKS 16
#define SROWS (SK / CHUNKS)   // 512 s-rows per block
#define TS 32                 // tile rows
#define TILES (SROWS / TS)    // 16

// pass2
#define P2_THREADS 256
#define P2_L 32                     // l rows per block
#define P2_ROWS (P2_L * HH)         // 256 (l,h) rows
#define QDSTRIDE 72                 // dup'd q row stride in floats (64 data + pad)
#define KSSTRIDE 33
#define P2_SMEM_FLOATS (P2_ROWS*QDSTRIDE + HH*KSSTRIDE + P2_ROWS)
#define P2_SMEM_BYTES (P2_SMEM_FLOATS * 4)

// Scratch (device globals: no allocation allowed)
__device__ __align__(16) float g_KV[NH * DD * DD];   // [nh][d][v]
__device__ __align__(16) float g_Ksum[NH * DD];      // [nh][d]

__device__ __forceinline__ float elu1(float x) {
    return x > 0.f ? x + 1.f : __expf(x);
}

__device__ __forceinline__ void fma2(unsigned long long &acc,
                                     unsigned long long a,
                                     unsigned long long b) {
    asm("fma.rn.f32x2 %0, %1, %2, %0;" : "+l"(acc) : "l"(a), "l"(b));
}
__device__ __forceinline__ unsigned long long pk(float x, float y) {
    unsigned long long r;
    asm("mov.b64 %0, {%1,%2};" : "=l"(r) : "f"(x), "f"(y));
    return r;
}
__device__ __forceinline__ float2 upk(unsigned long long v) {
    float2 r;
    asm("mov.b64 {%0,%1}, %2;" : "=f"(r.x), "=f"(r.y) : "l"(v));
    return r;
}

__global__ void zero_kernel() {
    int i = blockIdx.x * blockDim.x + threadIdx.x;
    if (i < NH * DD * DD) g_KV[i] = 0.f;
    if (i < NH * DD)      g_Ksum[i] = 0.f;
}

// ---------------------------------------------------------------------------
// Pass 1: identical to R6 (byte-for-byte) so R6's total decomposes.
// ---------------------------------------------------------------------------
__global__ __launch_bounds__(256, 2) void pass1(const float* __restrict__ keys,
                                                const float* __restrict__ values) {
    __shared__ __align__(16) float sm[8192];
    __shared__ __align__(16) float4 sKsum[256];

    const int nh = blockIdx.y;
    const int n = nh / HH, h = nh % HH;
    const int tid = threadIdx.x;
    const int w = tid >> 5, lane = tid & 31;
    const int half = lane >> 4;
    const int vp = lane & 15;
    const int r = tid >> 3;
    const int c4 = (tid & 7) * 4;

    unsigned long long acc[DD];
#pragma unroll
    for (int d = 0; d < DD; ++d) acc[d] = 0ull;
    float4 ksacc = make_float4(0.f, 0.f, 0.f, 0.f);

    const size_t base = ((size_t)n * SK * HH + h) * DD;
    const int rs = HH * DD;
    const int s_begin = blockIdx.x * SROWS;

    const float* kptr = keys   + base + (size_t)(s_begin + r) * rs + c4;
    const float* vptr = values + base + (size_t)(s_begin + r) * rs + c4;

    float4 kq = *(const float4*)kptr;
    float4 vq = *(const float4*)vptr;

    for (int t = 0; t < TILES; ++t) {
        float* kd = sm + (t & 1) * 2048;
        float* vd = sm + 4096 + (t & 1) * 1024;

        const float k0 = elu1(kq.x), k1 = elu1(kq.y), k2 = elu1(kq.z), k3 = elu1(kq.w);
        ksacc.x += k0; ksacc.y += k1; ksacc.z += k2; ksacc.w += k3;
        *(float4*)&kd[r * 64 + c4 * 2]     = make_float4(k0, k0, k1, k1);
        *(float4*)&kd[r * 64 + c4 * 2 + 4] = make_float4(k2, k2, k3, k3);
        *(float4*)&vd[r * 32 + c4] = vq;

        if (t + 1 < TILES) {
            kq = *(const float4*)(kptr + (size_t)(t + 1) * TS * rs);
            vq = *(const float4*)(vptr + (size_t)(t + 1) * TS * rs);
        }
        __syncthreads();

#pragma unroll
        for (int step = 0; step < 2; ++step) {
            const int row = w * 4 + step * 2 + half;
            const unsigned long long vv = *(const unsigned long long*)&vd[row * 32 + vp * 2];
            const ulonglong2* krow = (const ulonglong2*)&kd[row * 64];
#pragma unroll
            for (int j = 0; j < 16; ++j) {
                const ulonglong2 kk = krow[j];
                fma2(acc[2 * j],     kk.x, vv);
                fma2(acc[2 * j + 1], kk.y, vv);
            }
        }
    }
    __syncthreads();

#pragma unroll
    for (int d = 0; d < DD; ++d) {
        float2 a = upk(acc[d]);
        a.x += __shfl_down_sync(0xffffffffu, a.x, 16);
        a.y += __shfl_down_sync(0xffffffffu, a.y, 16);
        acc[d] = pk(a.x, a.y);
    }

    if (half == 0) {
#pragma unroll
        for (int d = 0; d < DD; ++d)
            *(unsigned long long*)&sm[w * 1024 + d * 32 + vp * 2] = acc[d];
    }
    __syncthreads();
    {
        float4 ssum = make_float4(0.f, 0.f, 0.f, 0.f);
#pragma unroll
        for (int ww = 0; ww < 8; ++ww) {
            const float4 vv = *(const float4*)&sm[ww * 1024 + tid * 4];
            ssum.x += vv.x; ssum.y += vv.y; ssum.z += vv.z; ssum.w += vv.w;
        }
        float* dst = &g_KV[nh * 1024 + tid * 4];
        atomicAdd(dst + 0, ssum.x);
        atomicAdd(dst + 1, ssum.y);
        atomicAdd(dst + 2, ssum.z);
        atomicAdd(dst + 3, ssum.w);
    }

    sKsum[tid] = ksacc;
    __syncthreads();
    if (tid < DD) {
        const int cgrp = tid >> 2;
        const int comp = tid & 3;
        float ssum = 0.f;
        for (int k = 0; k < 32; ++k) {
            const float4 vk = sKsum[cgrp + 8 * k];
            ssum += (comp == 0) ? vk.x : (comp == 1) ? vk.y : (comp == 2) ? vk.z : vk.w;
        }
        atomicAdd(&g_Ksum[nh * DD + tid], ssum);
    }
}

// ---------------------------------------------------------------------------
// Pass 2: identical to R6 (byte-for-byte). Launched 3x this round purely to
// decompose total time: T5 = z + p1 + 3*p2. Writing identical data to d_out
// multiple times is deterministic and graph-safe.
// ---------------------------------------------------------------------------
__global__ __launch_bounds__(P2_THREADS, 2) void pass2(const float* __restrict__ queries,
                                                       float* __restrict__ out) {
    extern __shared__ __align__(16) float dyn[];
    float* sQd  = dyn;
    float* sKs  = dyn + P2_ROWS * QDSTRIDE;
    float* sInv = sKs + HH * KSSTRIDE;

    const int n  = blockIdx.y;
    const int l0 = blockIdx.x * P2_L;
    const int tid = threadIdx.x;
    const int w = tid >> 5, lane = tid & 31;
    const int half = lane >> 4;
    const int vp = lane & 15;

    unsigned long long kvr[DD];
    {
        const float* kvh = &g_KV[(size_t)(n * HH + w) * DD * DD];
#pragma unroll
        for (int d = 0; d < DD; ++d)
            kvr[d] = *(const unsigned long long*)(kvh + d * DD + vp * 2);
    }

    const float* qsrc = queries + ((size_t)n * LQ + l0) * (HH * DD);
#pragma unroll
    for (int i = 0; i < 8; ++i) {
        const int f4 = tid + P2_THREADS * i;
        const float4 qv = *(const float4*)(qsrc + (size_t)f4 * 4);
        const float e0 = elu1(qv.x), e1 = elu1(qv.y), e2 = elu1(qv.z), e3 = elu1(qv.w);
        const int row = f4 >> 3, cc = (f4 & 7) * 4;
        *(float4*)&sQd[row * QDSTRIDE + cc * 2]     = make_float4(e0, e0, e1, e1);
        *(float4*)&sQd[row * QDSTRIDE + cc * 2 + 4] = make_float4(e2, e2, e3, e3);
    }
    {
        const int h2 = tid >> 5, d = tid & 31;
        sKs[h2 * KSSTRIDE + d] = g_Ksum[(n * HH + h2) * DD + d];
    }
    __syncthreads();

    {
        const int h2 = tid & 7;
        const float* qrow = &sQd[tid * QDSTRIDE];
        const float* ksh = &sKs[h2 * KSSTRIDE];
        float z = EPSV;
#pragma unroll
        for (int j = 0; j < 16; ++j) {
            const float4 qq = *(const float4*)(qrow + j * 4);
            z += qq.x * ksh[2 * j] + qq.z * ksh[2 * j + 1];
        }
        sInv[tid] = 1.0f / z;
    }
    __syncthreads();

#pragma unroll 4
    for (int step = 0; step < P2_L / 2; ++step) {
        const int row = (step * 2 + half) * HH + w;
        const ulonglong2* qrow = (const ulonglong2*)&sQd[row * QDSTRIDE];
        unsigned long long a0 = 0ull, a1 = 0ull;
#pragma unroll
        for (int j = 0; j < 8; ++j) {
            const ulonglong2 q01 = qrow[2 * j];
            const ulonglong2 q23 = qrow[2 * j + 1];
            fma2(a0, q01.x, kvr[4 * j]);
            fma2(a1, q01.y, kvr[4 * j + 1]);
            fma2(a0, q23.x, kvr[4 * j + 2]);
            fma2(a1, q23.y, kvr[4 * j + 3]);
        }
        const float inv = sInv[row];
        const float2 r0 = upk(a0);
        const float2 r1 = upk(a1);
        float* orow = out + ((size_t)n * LQ + l0) * (HH * DD) + (size_t)row * DD + vp * 2;
        *(float2*)orow = make_float2((r0.x + r1.x) * inv, (r0.y + r1.y) * inv);
    }
}

extern "C" void kernel_launch(void* const* d_in, const int* in_sizes, int n_in,
                              void* d_out, int out_size) {
    (void)in_sizes; (void)n_in; (void)out_size;
    const float* q = (const float*)d_in[0];
    const float* k = (const float*)d_in[1];
    const float* v = (const float*)d_in[2];
    float* out = (float*)d_out;

    zero_kernel<<<(NH * DD * DD + 255) / 256, 256>>>();
    pass1<<<dim3(CHUNKS, NH), 256>>>(k, v);
    cudaFuncSetAttribute(pass2, cudaFuncAttributeMaxDynamicSharedMemorySize, P2_SMEM_BYTES);
    // DIAGNOSTIC: pass2 x3 (idempotent). T5 = z + p1 + 3*p2 vs R6's
    // T3 = z + p1 + p2 = 152.3us  =>  p2 = (T5 - 152.3)/2, p1 = 148.3 - p2.
    // Period-5 launch pattern also moves the fixed ncu capture slot off
    // zero_kernel so a real kernel gets profiled.
    pass2<<<dim3(LQ / P2_L, NB), P2_THREADS, P2_SMEM_BYTES>>>(q, out);
    pass2<<<dim3(LQ / P2_L, NB), P2_THREADS, P2_SMEM_BYTES>>>(q, out);
    pass2<<<dim3(LQ / P2_L, NB), P2_THREADS, P2_SMEM_BYTES>>>(q, out);
}

// round 8
// speedup vs baseline: 2.3309x; 2.3309x over previous
#include <cuda_runtime.h>
#include <cstdint>

#define NB 8
#define LQ 8192
#define SK 8192
#define HH 8
#define DD 32
#define NH (NB*HH)
#define EPSV 1e-6f

// pass1
#define CHUNKS 16
#define SROWS (SK / CHUNKS)   // 512 s-rows per block
#define TS 32                 // tile rows
#define TILES (SROWS / TS)    // 16

// pass2
#define P2_THREADS 256
#define P2_L 32                       // l rows per block
#define QSTR 33                       // odd stride for q planes (LDS.32 reads)
#define KVSTR 36                      // 16B-aligned stride for kv rows
#define SQH_PLANE (P2_L * QSTR)       // 1056
#define SKV_PLANE (DD * KVSTR)        // 1152
#define P2_SMEM_FLOATS (HH*SQH_PLANE + HH*SKV_PLANE + HH*QSTR + P2_L*HH)
#define P2_SMEM_BYTES (P2_SMEM_FLOATS * 4)

// Scratch (device globals: no allocation allowed)
__device__ __align__(16) float g_KV[NH * DD * DD];   // [nh][d][v]
__device__ __align__(16) float g_Ksum[NH * DD];      // [nh][d]

__device__ __forceinline__ float elu1(float x) {
    return x > 0.f ? x + 1.f : __expf(x);
}

__device__ __forceinline__ void fma2(unsigned long long &acc,
                                     unsigned long long a,
                                     unsigned long long b) {
    asm("fma.rn.f32x2 %0, %1, %2, %0;" : "+l"(acc) : "l"(a), "l"(b));
}
__device__ __forceinline__ unsigned long long pk(float x, float y) {
    unsigned long long r;
    asm("mov.b64 %0, {%1,%2};" : "=l"(r) : "f"(x), "f"(y));
    return r;
}
__device__ __forceinline__ float2 upk(unsigned long long v) {
    float2 r;
    asm("mov.b64 {%0,%1}, %2;" : "=f"(r.x), "=f"(r.y) : "l"(v));
    return r;
}

__global__ void zero_kernel() {
    int i = blockIdx.x * blockDim.x + threadIdx.x;
    if (i < NH * DD * DD) g_KV[i] = 0.f;
    if (i < NH * DD)      g_Ksum[i] = 0.f;
}

// ---------------------------------------------------------------------------
// Pass 1: KV[nh] += sum_s outer(eluK_s, v_s);  Ksum[nh] += sum_s eluK_s
// 256 thr = 8 warps; each warp covers the full 32x32 outer product per s-row
// with a balanced 4(d) x 8(v) lane tile: per s-row per lane 48B LDS
// (k:16B, v:32B), 4 pk MOVs, 16 FFMA2.  K and V stored PLAIN in smem.
// ---------------------------------------------------------------------------
__global__ __launch_bounds__(256, 4) void pass1(const float* __restrict__ keys,
                                                const float* __restrict__ values) {
    // k0 [0,1024) k1 [1024,2048) v0 [2048,3072) v1 [3072,4096)
    // overlay after mainloop: sRed [0..8192) as [8][1024]
    __shared__ __align__(16) float sm[8192];
    __shared__ __align__(16) float4 sKsum[256];

    const int nh = blockIdx.y;
    const int n = nh / HH, h = nh % HH;
    const int tid = threadIdx.x;
    const int w = tid >> 5, lane = tid & 31;
    const int dg = lane & 7;          // d-group: d = dg*4 + i
    const int vg = lane >> 3;         // v-group: v = vg*8 + 2j(+1)
    const int r = tid >> 3;           // loader row 0..31
    const int c4 = (tid & 7) * 4;     // loader col group

    unsigned long long acc[4][4];     // [i:d][j:v-pair]
#pragma unroll
    for (int i = 0; i < 4; ++i)
#pragma unroll
        for (int j = 0; j < 4; ++j) acc[i][j] = 0ull;
    float4 ksacc = make_float4(0.f, 0.f, 0.f, 0.f);

    const size_t base = ((size_t)n * SK * HH + h) * DD;
    const int rs = HH * DD;
    const int s_begin = blockIdx.x * SROWS;

    const float* kptr = keys   + base + (size_t)(s_begin + r) * rs + c4;
    const float* vptr = values + base + (size_t)(s_begin + r) * rs + c4;

    float4 kq = *(const float4*)kptr;
    float4 vq = *(const float4*)vptr;

    for (int t = 0; t < TILES; ++t) {
        float* kd = sm + (t & 1) * 1024;
        float* vd = sm + 2048 + (t & 1) * 1024;

        const float k0 = elu1(kq.x), k1 = elu1(kq.y), k2 = elu1(kq.z), k3 = elu1(kq.w);
        ksacc.x += k0; ksacc.y += k1; ksacc.z += k2; ksacc.w += k3;
        *(float4*)&kd[r * 32 + c4] = make_float4(k0, k1, k2, k3);
        *(float4*)&vd[r * 32 + c4] = vq;

        if (t + 1 < TILES) {
            kq = *(const float4*)(kptr + (size_t)(t + 1) * TS * rs);
            vq = *(const float4*)(vptr + (size_t)(t + 1) * TS * rs);
        }
        __syncthreads();

        // warp w: s-rows w*4 .. w*4+3
#pragma unroll
        for (int rr = 0; rr < 4; ++rr) {
            const int s = w * 4 + rr;
            const float4 k4 = *(const float4*)&kd[s * 32 + dg * 4];
            const ulonglong2 va = *(const ulonglong2*)&vd[s * 32 + vg * 8];
            const ulonglong2 vb = *(const ulonglong2*)&vd[s * 32 + vg * 8 + 4];
            const unsigned long long kk[4] = {pk(k4.x, k4.x), pk(k4.y, k4.y),
                                              pk(k4.z, k4.z), pk(k4.w, k4.w)};
            const unsigned long long vv[4] = {va.x, va.y, vb.x, vb.y};
#pragma unroll
            for (int i = 0; i < 4; ++i)
#pragma unroll
                for (int j = 0; j < 4; ++j) fma2(acc[i][j], kk[i], vv[j]);
        }
        // next STS targets the other buffer; no trailing sync needed
    }
    __syncthreads();

    // dump warp replica to smem: element (d,v) at sm[w*1024 + d*32 + v]
#pragma unroll
    for (int i = 0; i < 4; ++i)
#pragma unroll
        for (int j = 0; j < 4; ++j)
            *(unsigned long long*)&sm[w * 1024 + (dg * 4 + i) * 32 + vg * 8 + 2 * j] = acc[i][j];
    __syncthreads();
    {
        float4 ssum = make_float4(0.f, 0.f, 0.f, 0.f);
#pragma unroll
        for (int ww = 0; ww < 8; ++ww) {
            const float4 vv = *(const float4*)&sm[ww * 1024 + tid * 4];
            ssum.x += vv.x; ssum.y += vv.y; ssum.z += vv.z; ssum.w += vv.w;
        }
        float* dst = &g_KV[nh * 1024 + tid * 4];
        atomicAdd(dst + 0, ssum.x);
        atomicAdd(dst + 1, ssum.y);
        atomicAdd(dst + 2, ssum.z);
        atomicAdd(dst + 3, ssum.w);
    }

    sKsum[tid] = ksacc;
    __syncthreads();
    if (tid < DD) {
        const int cgrp = tid >> 2;
        const int comp = tid & 3;
        float ssum = 0.f;
        for (int k = 0; k < 32; ++k) {
            const float4 vk = sKsum[cgrp + 8 * k];
            ssum += (comp == 0) ? vk.x : (comp == 1) ? vk.y : (comp == 2) ? vk.z : vk.w;
        }
        atomicAdd(&g_Ksum[nh * DD + tid], ssum);
    }
}

// ---------------------------------------------------------------------------
// Pass 2: out[l,h,:] = (eluQ @ KV_h) / (eluQ . Ksum_h + eps)
// grid (LQ/32, NB), 256 thr = 8 warps; warp w = head w, covers 32 l x 32 v
// with a balanced 4(l) x 8(v) lane tile. Q in per-head odd-stride planes
// (LDS.32), KV plain in smem (LDS.128). Per d-step/lane: 16B q + 32B kv,
// 4 pk, 16 FFMA2.
// ---------------------------------------------------------------------------
__global__ __launch_bounds__(P2_THREADS, 3) void pass2(const float* __restrict__ queries,
                                                       float* __restrict__ out) {
    extern __shared__ __align__(16) float dyn[];
    float* sQ   = dyn;                               // 8 heads x 32 l x QSTR
    float* sKV  = dyn + HH * SQH_PLANE;              // 8 heads x 32 d x KVSTR
    float* sKs  = sKV + HH * SKV_PLANE;              // 8 heads x QSTR
    float* sInv = sKs + HH * QSTR;                   // 8 heads x 32 l

    const int n  = blockIdx.y;
    const int l0 = blockIdx.x * P2_L;
    const int tid = threadIdx.x;
    const int w = tid >> 5, lane = tid & 31;
    const int lg = lane >> 2;         // l-group: l = lg*4 + i
    const int vg = lane & 3;          // v-group: v = vg*8 + 2j(+1)

    // stage KV (plain, padded rows) + Ksum
    const float* kvsrc = &g_KV[(size_t)(n * HH) * DD * DD];
#pragma unroll
    for (int i = 0; i < 8; ++i) {
        const int f4 = tid + P2_THREADS * i;         // 0..2047
        const int hh = f4 >> 8;
        const int d  = (f4 >> 3) & 31;
        const int c  = (f4 & 7) * 4;
        *(float4*)&sKV[hh * SKV_PLANE + d * KVSTR + c] = *(const float4*)(kvsrc + f4 * 4);
    }
    {
        const int hh = tid >> 5, d = tid & 31;
        sKs[hh * QSTR + d] = g_Ksum[(n * HH + hh) * DD + d];
    }

    // stage Q (elu applied) into per-head planes, odd stride
    const float* qsrc = queries + ((size_t)n * LQ + l0) * (HH * DD);
#pragma unroll
    for (int i = 0; i < 8; ++i) {
        const int f4 = tid + P2_THREADS * i;         // 0..2047
        const float4 qv = *(const float4*)(qsrc + (size_t)f4 * 4);
        const int l  = f4 >> 6;
        const int hh = (f4 >> 3) & 7;
        const int c  = (f4 & 7) * 4;
        float* dst = &sQ[hh * SQH_PLANE + l * QSTR + c];
        dst[0] = elu1(qv.x); dst[1] = elu1(qv.y);
        dst[2] = elu1(qv.z); dst[3] = elu1(qv.w);
    }
    __syncthreads();

    // z per row: warp w handles its head's 32 rows, lane = l
    {
        const float* qrow = &sQ[w * SQH_PLANE + lane * QSTR];
        const float* ksh  = &sKs[w * QSTR];
        float z = EPSV;
#pragma unroll
        for (int d = 0; d < DD; ++d) z += qrow[d] * ksh[d];
        sInv[w * P2_L + lane] = 1.0f / z;
    }
    __syncthreads();

    // main loop over d
    unsigned long long acc[4][4];     // [i:l][j:v-pair]
#pragma unroll
    for (int i = 0; i < 4; ++i)
#pragma unroll
        for (int j = 0; j < 4; ++j) acc[i][j] = 0ull;

    const float* qpl = &sQ[w * SQH_PLANE + lg * 4 * QSTR];
    const float* kvp = &sKV[w * SKV_PLANE + vg * 8];
#pragma unroll
    for (int d = 0; d < DD; ++d) {
        const float q0 = qpl[0 * QSTR + d];
        const float q1 = qpl[1 * QSTR + d];
        const float q2 = qpl[2 * QSTR + d];
        const float q3 = qpl[3 * QSTR + d];
        const ulonglong2 ka = *(const ulonglong2*)(kvp + d * KVSTR);
        const ulonglong2 kb = *(const ulonglong2*)(kvp + d * KVSTR + 4);
        const unsigned long long qq[4] = {pk(q0, q0), pk(q1, q1), pk(q2, q2), pk(q3, q3)};
        const unsigned long long vv[4] = {ka.x, ka.y, kb.x, kb.y};
#pragma unroll
        for (int i = 0; i < 4; ++i)
#pragma unroll
            for (int j = 0; j < 4; ++j) fma2(acc[i][j], qq[i], vv[j]);
    }

    // scale + store: row l = lg*4+i, 8 consecutive v at vg*8
#pragma unroll
    for (int i = 0; i < 4; ++i) {
        const int l = lg * 4 + i;
        const float inv = sInv[w * P2_L + l];
        const float2 a0 = upk(acc[i][0]);
        const float2 a1 = upk(acc[i][1]);
        const float2 a2 = upk(acc[i][2]);
        const float2 a3 = upk(acc[i][3]);
        float* orow = out + (((size_t)n * LQ + l0 + l) * HH + w) * DD + vg * 8;
        *(float4*)(orow)     = make_float4(a0.x * inv, a0.y * inv, a1.x * inv, a1.y * inv);
        *(float4*)(orow + 4) = make_float4(a2.x * inv, a2.y * inv, a3.x * inv, a3.y * inv);
    }
}

extern "C" void kernel_launch(void* const* d_in, const int* in_sizes, int n_in,
                              void* d_out, int out_size) {
    (void)in_sizes; (void)n_in; (void)out_size;
    const float* q = (const float*)d_in[0];
    const float* k = (const float*)d_in[1];
    const float* v = (const float*)d_in[2];
    float* out = (float*)d_out;

    zero_kernel<<<(NH * DD * DD + 255) / 256, 256>>>();
    pass1<<<dim3(CHUNKS, NH), 256>>>(k, v);
    cudaFuncSetAttribute(pass2, cudaFuncAttributeMaxDynamicSharedMemorySize, P2_SMEM_BYTES);
    pass2<<<dim3(LQ / P2_L, NB), P2_THREADS, P2_SMEM_BYTES>>>(q, out);
}

// round 11
// speedup vs baseline: 2.4857x; 1.0664x over previous
#include <cuda_runtime.h>
#include <cstdint>

#define NB 8
#define LQ 8192
#define SK 8192
#define HH 8
#define DD 32
#define NH (NB*HH)
#define EPSV 1e-6f

// pass1
#define CHUNKS 16
#define SROWS (SK / CHUNKS)   // 512 s-rows per block
#define TS 64                 // tile rows
#define TILES (SROWS / TS)    // 8

// pass2
#define P2_THREADS 256
#define P2_L 32                       // l rows per block
#define QSTR 33                       // odd stride for q planes (LDS.32 reads)
#define KVSTR 36                      // 16B-aligned stride for kv rows
#define SQH_PLANE (P2_L * QSTR)       // 1056
#define SKV_PLANE (DD * KVSTR)        // 1152
#define P2_SMEM_FLOATS (HH*SQH_PLANE + HH*SKV_PLANE + HH*QSTR + P2_L*HH)
#define P2_SMEM_BYTES (P2_SMEM_FLOATS * 4)

// Scratch (device globals: no allocation allowed).
// Per-chunk partials: written by plain stores (no pre-zeroing, no atomics).
__device__ __align__(16) float g_KVpart[CHUNKS][NH][DD * DD];  // 4 MB
__device__ __align__(16) float g_KSpart[CHUNKS][NH][DD];       // 128 KB
__device__ __align__(16) float g_KV[NH * DD * DD];             // [nh][d][v]
__device__ __align__(16) float g_Ksum[NH * DD];                // [nh][d]

__device__ __forceinline__ float elu1(float x) {
    return x > 0.f ? x + 1.f : __expf(x);
}

__device__ __forceinline__ void fma2(unsigned long long &acc,
                                     unsigned long long a,
                                     unsigned long long b) {
    asm("fma.rn.f32x2 %0, %1, %2, %0;" : "+l"(acc) : "l"(a), "l"(b));
}
__device__ __forceinline__ unsigned long long pk(float x, float y) {
    unsigned long long r;
    asm("mov.b64 %0, {%1,%2};" : "=l"(r) : "f"(x), "f"(y));
    return r;
}
__device__ __forceinline__ float2 upk(unsigned long long v) {
    float2 r;
    asm("mov.b64 {%0,%1}, %2;" : "=f"(r.x), "=f"(r.y) : "l"(v));
    return r;
}

// ---------------------------------------------------------------------------
// Pass 1: KVpart[chunk][nh] = sum_{s in chunk} outer(eluK_s, v_s)
// 256 thr = 8 warps; 64-row double-buffered tiles; warp covers the full 32x32
// outer product with a balanced 4(d) x 8(v) lane tile (48B LDS / 16 FFMA2 per
// s-row per lane). Plain partial stores at the end — no atomics.
// ---------------------------------------------------------------------------
__global__ __launch_bounds__(256, 3) void pass1(const float* __restrict__ keys,
                                                const float* __restrict__ values) {
    // k0 [0,2048) k1 [2048,4096) v0 [4096,6144) v1 [6144,8192)
    // overlay after mainloop: sRed [0..8192) as [8][1024]
    __shared__ __align__(16) float sm[8192];
    __shared__ __align__(16) float4 sKsum[256];

    const int nh = blockIdx.y;
    const int n = nh / HH, h = nh % HH;
    const int chunk = blockIdx.x;
    const int tid = threadIdx.x;
    const int w = tid >> 5, lane = tid & 31;
    const int dg = lane & 7;          // d-group: d = dg*4 + i
    const int vg = lane >> 3;         // v-group: v = vg*8 + 2j(+1)
    const int r = tid >> 3;           // loader row 0..31 (also handles r+32)
    const int c4 = (tid & 7) * 4;     // loader col group

    unsigned long long acc[4][4];     // [i:d][j:v-pair]
#pragma unroll
    for (int i = 0; i < 4; ++i)
#pragma unroll
        for (int j = 0; j < 4; ++j) acc[i][j] = 0ull;
    float4 ksacc = make_float4(0.f, 0.f, 0.f, 0.f);

    const size_t base = ((size_t)n * SK * HH + h) * DD;
    const int rs = HH * DD;           // 256 floats between s-rows
    const int s_begin = chunk * SROWS;

    const float* kptr = keys   + base + (size_t)(s_begin + r) * rs + c4;
    const float* vptr = values + base + (size_t)(s_begin + r) * rs + c4;
    const size_t half_off = (size_t)32 * rs;

    float4 kqa = *(const float4*)kptr;
    float4 kqb = *(const float4*)(kptr + half_off);
    float4 vqa = *(const float4*)vptr;
    float4 vqb = *(const float4*)(vptr + half_off);

    for (int t = 0; t < TILES; ++t) {
        float* kd = sm + (t & 1) * 2048;
        float* vd = sm + 4096 + (t & 1) * 2048;

        const float a0 = elu1(kqa.x), a1 = elu1(kqa.y), a2 = elu1(kqa.z), a3 = elu1(kqa.w);
        const float b0 = elu1(kqb.x), b1 = elu1(kqb.y), b2 = elu1(kqb.z), b3 = elu1(kqb.w);
        ksacc.x += a0 + b0; ksacc.y += a1 + b1;
        ksacc.z += a2 + b2; ksacc.w += a3 + b3;
        *(float4*)&kd[r * 32 + c4]        = make_float4(a0, a1, a2, a3);
        *(float4*)&kd[(r + 32) * 32 + c4] = make_float4(b0, b1, b2, b3);
        *(float4*)&vd[r * 32 + c4]        = vqa;
        *(float4*)&vd[(r + 32) * 32 + c4] = vqb;

        if (t + 1 < TILES) {
            const size_t adv = (size_t)(t + 1) * TS * rs;
            kqa = *(const float4*)(kptr + adv);
            kqb = *(const float4*)(kptr + adv + half_off);
            vqa = *(const float4*)(vptr + adv);
            vqb = *(const float4*)(vptr + adv + half_off);
        }
        __syncthreads();

        // warp w: s-rows w*8 .. w*8+7
#pragma unroll
        for (int rr = 0; rr < 8; ++rr) {
            const int s = w * 8 + rr;
            const float4 k4 = *(const float4*)&kd[s * 32 + dg * 4];
            const ulonglong2 va = *(const ulonglong2*)&vd[s * 32 + vg * 8];
            const ulonglong2 vb = *(const ulonglong2*)&vd[s * 32 + vg * 8 + 4];
            const unsigned long long kk[4] = {pk(k4.x, k4.x), pk(k4.y, k4.y),
                                              pk(k4.z, k4.z), pk(k4.w, k4.w)};
            const unsigned long long vv[4] = {va.x, va.y, vb.x, vb.y};
#pragma unroll
            for (int i = 0; i < 4; ++i)
#pragma unroll
                for (int j = 0; j < 4; ++j) fma2(acc[i][j], kk[i], vv[j]);
        }
        // next STS targets the other buffer; no trailing sync needed
    }
    __syncthreads();

    // dump warp replica to smem overlay: element (d,v) at sm[w*1024 + d*32 + v]
#pragma unroll
    for (int i = 0; i < 4; ++i)
#pragma unroll
        for (int j = 0; j < 4; ++j)
            *(unsigned long long*)&sm[w * 1024 + (dg * 4 + i) * 32 + vg * 8 + 2 * j] = acc[i][j];
    __syncthreads();
    {
        float4 ssum = make_float4(0.f, 0.f, 0.f, 0.f);
#pragma unroll
        for (int ww = 0; ww < 8; ++ww) {
            const float4 vv = *(const float4*)&sm[ww * 1024 + tid * 4];
            ssum.x += vv.x; ssum.y += vv.y; ssum.z += vv.z; ssum.w += vv.w;
        }
        *(float4*)&g_KVpart[chunk][nh][tid * 4] = ssum;
    }

    sKsum[tid] = ksacc;
    __syncthreads();
    if (tid < DD) {
        const int cgrp = tid >> 2;
        const int comp = tid & 3;
        float ssum = 0.f;
        for (int k = 0; k < 32; ++k) {
            const float4 vk = sKsum[cgrp + 8 * k];
            ssum += (comp == 0) ? vk.x : (comp == 1) ? vk.y : (comp == 2) ? vk.z : vk.w;
        }
        g_KSpart[chunk][nh][tid] = ssum;
    }
}

// ---------------------------------------------------------------------------
// Reduce: fold 16 chunk partials -> g_KV, g_Ksum.  64 blocks x 256 thr,
// reads 4 MB (L2-resident), ~3us.
// ---------------------------------------------------------------------------
__global__ __launch_bounds__(256) void reduce_kernel() {
    const int nh = blockIdx.x;
    const int tid = threadIdx.x;
    float4 s = make_float4(0.f, 0.f, 0.f, 0.f);
#pragma unroll
    for (int c = 0; c < CHUNKS; ++c) {
        const float4 p = *(const float4*)&g_KVpart[c][nh][tid * 4];
        s.x += p.x; s.y += p.y; s.z += p.z; s.w += p.w;
    }
    *(float4*)&g_KV[nh * DD * DD + tid * 4] = s;
    if (tid < DD) {
        float ks = 0.f;
#pragma unroll
        for (int c = 0; c < CHUNKS; ++c) ks += g_KSpart[c][nh][tid];
        g_Ksum[nh * DD + tid] = ks;
    }
}

// ---------------------------------------------------------------------------
// Pass 2: out[l,h,:] = (eluQ @ KV_h) / (eluQ . Ksum_h + eps)
// (unchanged from R8: balanced 4(l) x 8(v) lane tile, per-head Q planes)
// ---------------------------------------------------------------------------
__global__ __launch_bounds__(P2_THREADS, 3) void pass2(const float* __restrict__ queries,
                                                       float* __restrict__ out) {
    extern __shared__ __align__(16) float dyn[];
    float* sQ   = dyn;                               // 8 heads x 32 l x QSTR
    float* sKV  = dyn + HH * SQH_PLANE;              // 8 heads x 32 d x KVSTR
    float* sKs  = sKV + HH * SKV_PLANE;              // 8 heads x QSTR
    float* sInv = sKs + HH * QSTR;                   // 8 heads x 32 l

    const int n  = blockIdx.y;
    const int l0 = blockIdx.x * P2_L;
    const int tid = threadIdx.x;
    const int w = tid >> 5, lane = tid & 31;
    const int lg = lane >> 2;         // l-group: l = lg*4 + i
    const int vg = lane & 3;          // v-group: v = vg*8 + 2j(+1)

    const float* kvsrc = &g_KV[(size_t)(n * HH) * DD * DD];
#pragma unroll
    for (int i = 0; i < 8; ++i) {
        const int f4 = tid + P2_THREADS * i;         // 0..2047
        const int hh = f4 >> 8;
        const int d  = (f4 >> 3) & 31;
        const int c  = (f4 & 7) * 4;
        *(float4*)&sKV[hh * SKV_PLANE + d * KVSTR + c] = *(const float4*)(kvsrc + f4 * 4);
    }
    {
        const int hh = tid >> 5, d = tid & 31;
        sKs[hh * QSTR + d] = g_Ksum[(n * HH + hh) * DD + d];
    }

    const float* qsrc = queries + ((size_t)n * LQ + l0) * (HH * DD);
#pragma unroll
    for (int i = 0; i < 8; ++i) {
        const int f4 = tid + P2_THREADS * i;         // 0..2047
        const float4 qv = *(const float4*)(qsrc + (size_t)f4 * 4);
        const int l  = f4 >> 6;
        const int hh = (f4 >> 3) & 7;
        const int c  = (f4 & 7) * 4;
        float* dst = &sQ[hh * SQH_PLANE + l * QSTR + c];
        dst[0] = elu1(qv.x); dst[1] = elu1(qv.y);
        dst[2] = elu1(qv.z); dst[3] = elu1(qv.w);
    }
    __syncthreads();

    {
        const float* qrow = &sQ[w * SQH_PLANE + lane * QSTR];
        const float* ksh  = &sKs[w * QSTR];
        float z = EPSV;
#pragma unroll
        for (int d = 0; d < DD; ++d) z += qrow[d] * ksh[d];
        sInv[w * P2_L + lane] = 1.0f / z;
    }
    __syncthreads();

    unsigned long long acc[4][4];     // [i:l][j:v-pair]
#pragma unroll
    for (int i = 0; i < 4; ++i)
#pragma unroll
        for (int j = 0; j < 4; ++j) acc[i][j] = 0ull;

    const float* qpl = &sQ[w * SQH_PLANE + lg * 4 * QSTR];
    const float* kvp = &sKV[w * SKV_PLANE + vg * 8];
#pragma unroll
    for (int d = 0; d < DD; ++d) {
        const float q0 = qpl[0 * QSTR + d];
        const float q1 = qpl[1 * QSTR + d];
        const float q2 = qpl[2 * QSTR + d];
        const float q3 = qpl[3 * QSTR + d];
        const ulonglong2 ka = *(const ulonglong2*)(kvp + d * KVSTR);
        const ulonglong2 kb = *(const ulonglong2*)(kvp + d * KVSTR + 4);
        const unsigned long long qq[4] = {pk(q0, q0), pk(q1, q1), pk(q2, q2), pk(q3, q3)};
        const unsigned long long vv[4] = {ka.x, ka.y, kb.x, kb.y};
#pragma unroll
        for (int i = 0; i < 4; ++i)
#pragma unroll
            for (int j = 0; j < 4; ++j) fma2(acc[i][j], qq[i], vv[j]);
    }

#pragma unroll
    for (int i = 0; i < 4; ++i) {
        const int l = lg * 4 + i;
        const float inv = sInv[w * P2_L + l];
        const float2 a0 = upk(acc[i][0]);
        const float2 a1 = upk(acc[i][1]);
        const float2 a2 = upk(acc[i][2]);
        const float2 a3 = upk(acc[i][3]);
        float* orow = out + (((size_t)n * LQ + l0 + l) * HH + w) * DD + vg * 8;
        *(float4*)(orow)     = make_float4(a0.x * inv, a0.y * inv, a1.x * inv, a1.y * inv);
        *(float4*)(orow + 4) = make_float4(a2.x * inv, a2.y * inv, a3.x * inv, a3.y * inv);
    }
}

extern "C" void kernel_launch(void* const* d_in, const int* in_sizes, int n_in,
                              void* d_out, int out_size) {
    (void)in_sizes; (void)n_in; (void)out_size;
    const float* q = (const float*)d_in[0];
    const float* k = (const float*)d_in[1];
    const float* v = (const float*)d_in[2];
    float* out = (float*)d_out;

    pass1<<<dim3(CHUNKS, NH), 256>>>(k, v);
    reduce_kernel<<<NH, 256>>>();
    cudaFuncSetAttribute(pass2, cudaFuncAttributeMaxDynamicSharedMemorySize, P2_SMEM_BYTES);
    pass2<<<dim3(LQ / P2_L, NB), P2_THREADS, P2_SMEM_BYTES>>>(q, out);
}

// round 12
// speedup vs baseline: 2.6353x; 1.0602x over previous
#include <cuda_runtime.h>
#include <cstdint>

#define NB 8
#define LQ 8192
#define SK 8192
#define HH 8
#define DD 32
#define NH (NB*HH)
#define EPSV 1e-6f

// pass1
#define CHUNKS 16
#define SROWS (SK / CHUNKS)   // 512 s-rows per block
#define TS 64                 // tile rows
#define TILES (SROWS / TS)    // 8

// pass2
#define P2_THREADS 256
#define P2_L 32                       // l rows per block
#define QSTR 33                       // odd stride for q planes (LDS.32 reads)
#define KVSTR 36                      // 16B-aligned stride for kv rows
#define SQH_PLANE (P2_L * QSTR)       // 1056
#define SKV_PLANE (DD * KVSTR)        // 1152
#define P2_SMEM_FLOATS (HH*SQH_PLANE + HH*SKV_PLANE + HH*QSTR + P2_L*HH)
#define P2_SMEM_BYTES (P2_SMEM_FLOATS * 4)

// Scratch (device globals: no allocation allowed).
__device__ __align__(16) float g_KVpart[CHUNKS][NH][DD * DD];  // 4 MB
__device__ __align__(16) float g_KSpart[CHUNKS][NH][DD];       // 128 KB
__device__ __align__(16) float g_KV[NH * DD * DD];             // [nh][d][v]
__device__ __align__(16) float g_Ksum[NH * DD];                // [nh][d]

__device__ __forceinline__ float elu1(float x) {
    return x > 0.f ? x + 1.f : __expf(x);
}

__device__ __forceinline__ void fma2(unsigned long long &acc,
                                     unsigned long long a,
                                     unsigned long long b) {
    asm("fma.rn.f32x2 %0, %1, %2, %0;" : "+l"(acc) : "l"(a), "l"(b));
}
__device__ __forceinline__ unsigned long long pk(float x, float y) {
    unsigned long long r;
    asm("mov.b64 %0, {%1,%2};" : "=l"(r) : "f"(x), "f"(y));
    return r;
}
__device__ __forceinline__ float2 upk(unsigned long long v) {
    float2 r;
    asm("mov.b64 {%0,%1}, %2;" : "=f"(r.x), "=f"(r.y) : "l"(v));
    return r;
}

__device__ __forceinline__ void cp16(uint32_t smem_dst, const void* gmem_src) {
    asm volatile("cp.async.cg.shared.global [%0], [%1], 16;"
                 :: "r"(smem_dst), "l"(gmem_src));
}
__device__ __forceinline__ void cp_commit() {
    asm volatile("cp.async.commit_group;");
}
__device__ __forceinline__ void cp_wait0() {
    asm volatile("cp.async.wait_group 0;");
}

// ---------------------------------------------------------------------------
// Pass 1: KVpart[chunk][nh] = sum_{s in chunk} outer(eluK_s, v_s)
// 256 thr = 8 warps; 64-row double-buffered tiles. V staged via cp.async
// (no register residency); K via registers with elu applied at STS.
// Warp covers full 32x32 per s-row with balanced 4(d) x 8(v) lane tile.
// ---------------------------------------------------------------------------
__global__ __launch_bounds__(256, 4) void pass1(const float* __restrict__ keys,
                                                const float* __restrict__ values) {
    // k0 [0,2048) k1 [2048,4096) v0 [4096,6144) v1 [6144,8192)  (floats)
    // overlay after mainloop: sRed [0..8192) as [8][1024]
    __shared__ __align__(16) float sm[8192];
    __shared__ __align__(16) float4 sKsum[256];

    const int nh = blockIdx.y;
    const int n = nh / HH, h = nh % HH;
    const int chunk = blockIdx.x;
    const int tid = threadIdx.x;
    const int w = tid >> 5, lane = tid & 31;
    const int dg = lane & 7;          // d-group: d = dg*4 + i
    const int vg = lane >> 3;         // v-group: v = vg*8 + 2j(+1)
    const int r = tid >> 3;           // loader row 0..31 (also r+32)
    const int c4 = (tid & 7) * 4;     // loader col group

    unsigned long long acc[4][4];     // [i:d][j:v-pair]
#pragma unroll
    for (int i = 0; i < 4; ++i)
#pragma unroll
        for (int j = 0; j < 4; ++j) acc[i][j] = 0ull;
    float4 ksacc = make_float4(0.f, 0.f, 0.f, 0.f);

    const size_t base = ((size_t)n * SK * HH + h) * DD;
    const int rs = HH * DD;           // 256 floats between s-rows
    const int s_begin = chunk * SROWS;

    const float* kptr = keys   + base + (size_t)(s_begin + r) * rs + c4;
    const float* vptr = values + base + (size_t)(s_begin + r) * rs + c4;
    const size_t half_off = (size_t)32 * rs;

    // smem addresses for this thread's staging slots
    const uint32_t vbase = (uint32_t)__cvta_generic_to_shared(&sm[4096]) +
                           (uint32_t)((r * 32 + c4) * 4);
    const uint32_t vbase2 = vbase + (uint32_t)(32 * 32 * 4);   // row r+32

    // ---- prologue ----
    // V(0) -> vbuf0 via cp.async
    cp16(vbase, vptr);
    cp16(vbase2, vptr + half_off);
    cp_commit();
    // K(0) -> regs
    float4 kqa = *(const float4*)kptr;
    float4 kqb = *(const float4*)(kptr + half_off);
    // stage K(0) with elu
    {
        const float a0 = elu1(kqa.x), a1 = elu1(kqa.y), a2 = elu1(kqa.z), a3 = elu1(kqa.w);
        const float b0 = elu1(kqb.x), b1 = elu1(kqb.y), b2 = elu1(kqb.z), b3 = elu1(kqb.w);
        ksacc.x += a0 + b0; ksacc.y += a1 + b1;
        ksacc.z += a2 + b2; ksacc.w += a3 + b3;
        *(float4*)&sm[r * 32 + c4]        = make_float4(a0, a1, a2, a3);
        *(float4*)&sm[(r + 32) * 32 + c4] = make_float4(b0, b1, b2, b3);
    }
    // K(1) -> regs
    if (TILES > 1) {
        kqa = *(const float4*)(kptr + (size_t)TS * rs);
        kqb = *(const float4*)(kptr + (size_t)TS * rs + half_off);
    }
    cp_wait0();
    __syncthreads();

    for (int t = 0; t < TILES; ++t) {
        // issue V(t+1) right after the barrier: every warp has finished
        // reading vbuf (t+1)&1 (== (t-1)&1) before this barrier.
        if (t + 1 < TILES) {
            const size_t adv = (size_t)(t + 1) * TS * rs;
            const uint32_t voff = (uint32_t)(((t + 1) & 1) * 2048 * 4);
            cp16(vbase + voff, vptr + adv);
            cp16(vbase2 + voff, vptr + adv + half_off);
            cp_commit();
        }

        // compute tile t
        {
            const float* kd = sm + (t & 1) * 2048;
            const float* vd = sm + 4096 + (t & 1) * 2048;
#pragma unroll
            for (int rr = 0; rr < 8; ++rr) {
                const int s = w * 8 + rr;
                const float4 k4 = *(const float4*)&kd[s * 32 + dg * 4];
                const ulonglong2 va = *(const ulonglong2*)&vd[s * 32 + vg * 8];
                const ulonglong2 vb = *(const ulonglong2*)&vd[s * 32 + vg * 8 + 4];
                const unsigned long long kk[4] = {pk(k4.x, k4.x), pk(k4.y, k4.y),
                                                  pk(k4.z, k4.z), pk(k4.w, k4.w)};
                const unsigned long long vv[4] = {va.x, va.y, vb.x, vb.y};
#pragma unroll
                for (int i = 0; i < 4; ++i)
#pragma unroll
                    for (int j = 0; j < 4; ++j) fma2(acc[i][j], kk[i], vv[j]);
            }
        }

        // stage K(t+1) (other buffer; readers of it passed the last barrier)
        if (t + 1 < TILES) {
            float* kd1 = sm + ((t + 1) & 1) * 2048;
            const float a0 = elu1(kqa.x), a1 = elu1(kqa.y), a2 = elu1(kqa.z), a3 = elu1(kqa.w);
            const float b0 = elu1(kqb.x), b1 = elu1(kqb.y), b2 = elu1(kqb.z), b3 = elu1(kqb.w);
            ksacc.x += a0 + b0; ksacc.y += a1 + b1;
            ksacc.z += a2 + b2; ksacc.w += a3 + b3;
            *(float4*)&kd1[r * 32 + c4]        = make_float4(a0, a1, a2, a3);
            *(float4*)&kd1[(r + 32) * 32 + c4] = make_float4(b0, b1, b2, b3);
            if (t + 2 < TILES) {      // K(t+2) -> regs
                const size_t adv2 = (size_t)(t + 2) * TS * rs;
                kqa = *(const float4*)(kptr + adv2);
                kqb = *(const float4*)(kptr + adv2 + half_off);
            }
            cp_wait0();               // V(t+1) landed
            __syncthreads();
        }
    }
    __syncthreads();

    // dump warp replica to smem overlay: element (d,v) at sm[w*1024 + d*32 + v]
#pragma unroll
    for (int i = 0; i < 4; ++i)
#pragma unroll
        for (int j = 0; j < 4; ++j)
            *(unsigned long long*)&sm[w * 1024 + (dg * 4 + i) * 32 + vg * 8 + 2 * j] = acc[i][j];
    __syncthreads();
    {
        float4 ssum = make_float4(0.f, 0.f, 0.f, 0.f);
#pragma unroll
        for (int ww = 0; ww < 8; ++ww) {
            const float4 vv = *(const float4*)&sm[ww * 1024 + tid * 4];
            ssum.x += vv.x; ssum.y += vv.y; ssum.z += vv.z; ssum.w += vv.w;
        }
        *(float4*)&g_KVpart[chunk][nh][tid * 4] = ssum;
    }

    sKsum[tid] = ksacc;
    __syncthreads();
    if (tid < DD) {
        const int cgrp = tid >> 2;
        const int comp = tid & 3;
        float ssum = 0.f;
        for (int k = 0; k < 32; ++k) {
            const float4 vk = sKsum[cgrp + 8 * k];
            ssum += (comp == 0) ? vk.x : (comp == 1) ? vk.y : (comp == 2) ? vk.z : vk.w;
        }
        g_KSpart[chunk][nh][tid] = ssum;
    }
}

// ---------------------------------------------------------------------------
// Reduce: fold 16 chunk partials -> g_KV, g_Ksum.
// ---------------------------------------------------------------------------
__global__ __launch_bounds__(256) void reduce_kernel() {
    const int nh = blockIdx.x;
    const int tid = threadIdx.x;
    float4 s = make_float4(0.f, 0.f, 0.f, 0.f);
#pragma unroll
    for (int c = 0; c < CHUNKS; ++c) {
        const float4 p = *(const float4*)&g_KVpart[c][nh][tid * 4];
        s.x += p.x; s.y += p.y; s.z += p.z; s.w += p.w;
    }
    *(float4*)&g_KV[nh * DD * DD + tid * 4] = s;
    if (tid < DD) {
        float ks = 0.f;
#pragma unroll
        for (int c = 0; c < CHUNKS; ++c) ks += g_KSpart[c][nh][tid];
        g_Ksum[nh * DD + tid] = ks;
    }
}

// ---------------------------------------------------------------------------
// Pass 2: unchanged from R11 (proven 57us share).
// ---------------------------------------------------------------------------
__global__ __launch_bounds__(P2_THREADS, 3) void pass2(const float* __restrict__ queries,
                                                       float* __restrict__ out) {
    extern __shared__ __align__(16) float dyn[];
    float* sQ   = dyn;                               // 8 heads x 32 l x QSTR
    float* sKV  = dyn + HH * SQH_PLANE;              // 8 heads x 32 d x KVSTR
    float* sKs  = sKV + HH * SKV_PLANE;              // 8 heads x QSTR
    float* sInv = sKs + HH * QSTR;                   // 8 heads x 32 l

    const int n  = blockIdx.y;
    const int l0 = blockIdx.x * P2_L;
    const int tid = threadIdx.x;
    const int w = tid >> 5, lane = tid & 31;
    const int lg = lane >> 2;         // l-group: l = lg*4 + i
    const int vg = lane & 3;          // v-group: v = vg*8 + 2j(+1)

    const float* kvsrc = &g_KV[(size_t)(n * HH) * DD * DD];
#pragma unroll
    for (int i = 0; i < 8; ++i) {
        const int f4 = tid + P2_THREADS * i;         // 0..2047
        const int hh = f4 >> 8;
        const int d  = (f4 >> 3) & 31;
        const int c  = (f4 & 7) * 4;
        *(float4*)&sKV[hh * SKV_PLANE + d * KVSTR + c] = *(const float4*)(kvsrc + f4 * 4);
    }
    {
        const int hh = tid >> 5, d = tid & 31;
        sKs[hh * QSTR + d] = g_Ksum[(n * HH + hh) * DD + d];
    }

    const float* qsrc = queries + ((size_t)n * LQ + l0) * (HH * DD);
#pragma unroll
    for (int i = 0; i < 8; ++i) {
        const int f4 = tid + P2_THREADS * i;         // 0..2047
        const float4 qv = *(const float4*)(qsrc + (size_t)f4 * 4);
        const int l  = f4 >> 6;
        const int hh = (f4 >> 3) & 7;
        const int c  = (f4 & 7) * 4;
        float* dst = &sQ[hh * SQH_PLANE + l * QSTR + c];
        dst[0] = elu1(qv.x); dst[1] = elu1(qv.y);
        dst[2] = elu1(qv.z); dst[3] = elu1(qv.w);
    }
    __syncthreads();

    {
        const float* qrow = &sQ[w * SQH_PLANE + lane * QSTR];
        const float* ksh  = &sKs[w * QSTR];
        float z = EPSV;
#pragma unroll
        for (int d = 0; d < DD; ++d) z += qrow[d] * ksh[d];
        sInv[w * P2_L + lane] = 1.0f / z;
    }
    __syncthreads();

    unsigned long long acc[4][4];     // [i:l][j:v-pair]
#pragma unroll
    for (int i = 0; i < 4; ++i)
#pragma unroll
        for (int j = 0; j < 4; ++j) acc[i][j] = 0ull;

    const float* qpl = &sQ[w * SQH_PLANE + lg * 4 * QSTR];
    const float* kvp = &sKV[w * SKV_PLANE + vg * 8];
#pragma unroll
    for (int d = 0; d < DD; ++d) {
        const float q0 = qpl[0 * QSTR + d];
        const float q1 = qpl[1 * QSTR + d];
        const float q2 = qpl[2 * QSTR + d];
        const float q3 = qpl[3 * QSTR + d];
        const ulonglong2 ka = *(const ulonglong2*)(kvp + d * KVSTR);
        const ulonglong2 kb = *(const ulonglong2*)(kvp + d * KVSTR + 4);
        const unsigned long long qq[4] = {pk(q0, q0), pk(q1, q1), pk(q2, q2), pk(q3, q3)};
        const unsigned long long vv[4] = {ka.x, ka.y, kb.x, kb.y};
#pragma unroll
        for (int i = 0; i < 4; ++i)
#pragma unroll
            for (int j = 0; j < 4; ++j) fma2(acc[i][j], qq[i], vv[j]);
    }

#pragma unroll
    for (int i = 0; i < 4; ++i) {
        const int l = lg * 4 + i;
        const float inv = sInv[w * P2_L + l];
        const float2 a0 = upk(acc[i][0]);
        const float2 a1 = upk(acc[i][1]);
        const float2 a2 = upk(acc[i][2]);
        const float2 a3 = upk(acc[i][3]);
        float* orow = out + (((size_t)n * LQ + l0 + l) * HH + w) * DD + vg * 8;
        *(float4*)(orow)     = make_float4(a0.x * inv, a0.y * inv, a1.x * inv, a1.y * inv);
        *(float4*)(orow + 4) = make_float4(a2.x * inv, a2.y * inv, a3.x * inv, a3.y * inv);
    }
}

extern "C" void kernel_launch(void* const* d_in, const int* in_sizes, int n_in,
                              void* d_out, int out_size) {
    (void)in_sizes; (void)n_in; (void)out_size;
    const float* q = (const float*)d_in[0];
    const float* k = (const float*)d_in[1];
    const float* v = (const float*)d_in[2];
    float* out = (float*)d_out;

    pass1<<<dim3(CHUNKS, NH), 256>>>(k, v);
    reduce_kernel<<<NH, 256>>>();
    cudaFuncSetAttribute(pass2, cudaFuncAttributeMaxDynamicSharedMemorySize, P2_SMEM_BYTES);
    pass2<<<dim3(LQ / P2_L, NB), P2_THREADS, P2_SMEM_BYTES>>>(q, out);
}